// round 8
// baseline (speedup 1.0000x reference)
#include <cuda_runtime.h>

#define MM   64      // nodes per graph
#define HH   128     // hidden
#define INF_ 3       // input feats
#define AA   64      // A
#define STR  132     // padded row stride for 64x128 tiles (floats)
#define ASTR 68      // padded row stride for attn 64x64 tile (floats) — 272B % 128B = 16
#define PSTR 264     // packed Wh2 row stride (floats): 128 cols * 2 + 8 pad
#define NT   512     // threads per CTA

typedef unsigned long long ull;

__device__ float g_c2l[HH], g_c2r[HH], g_c1l[INF_], g_c1r[INF_];
__device__ __align__(16) float g_W2pk[64 * HH * 2];   // k-interleaved W2: [pk][c] -> (W2[2pk][c], W2[2pk+1][c])

__device__ __forceinline__ void ffma2(ull& d, ull a, ull b) {
    asm("fma.rn.f32x2 %0, %1, %2, %3;" : "=l"(d) : "l"(a), "l"(b), "l"(d));
}
__device__ __forceinline__ float2 unpk(ull v) {
    float2 r;
    asm("mov.b64 {%0, %1}, %2;" : "=f"(r.x), "=f"(r.y) : "l"(v));
    return r;
}

__global__ void precomp_kernel(const float* __restrict__ W1, const float* __restrict__ a1,
                               const float* __restrict__ W2, const float* __restrict__ a2) {
    int t = threadIdx.x;  // 128 threads
    float s1 = 0.f, s2 = 0.f;
#pragma unroll 8
    for (int j = 0; j < HH; j++) {
        float w = W2[t * HH + j];
        s1 = fmaf(w, a2[j], s1);
        s2 = fmaf(w, a2[HH + j], s2);
    }
    g_c2l[t] = s1;
    g_c2r[t] = s2;
    if (t < INF_) {
        float p = 0.f, q = 0.f;
#pragma unroll 8
        for (int j = 0; j < HH; j++) {
            float w = W1[t * HH + j];
            p = fmaf(w, a1[j], p);
            q = fmaf(w, a1[HH + j], q);
        }
        g_c1l[t] = p;
        g_c1r[t] = q;
    }
    // Build k-interleaved W2 (pk in [0,64), c in [0,128))
    for (int idx = t; idx < 64 * HH; idx += 128) {
        int pkk = idx >> 7, c = idx & 127;
        g_W2pk[idx * 2 + 0] = W2[(2 * pkk) * HH + c];
        g_W2pk[idx * 2 + 1] = W2[(2 * pkk + 1) * HH + c];
    }
}

// Softmax over 64 cols, 8 lanes per row (512 threads -> 64 rows x 8 lanes).
__device__ __forceinline__ void softmax64_w8(float* __restrict__ sAt,
                                             const float* __restrict__ sSi,
                                             const float* __restrict__ sSj, int tid) {
    int row = tid >> 3, lane = tid & 7;
    float si = sSi[row];
    const float* sj = sSj + lane * 8;
    float ev[8];
    float m = -1e30f;
#pragma unroll
    for (int j = 0; j < 8; j++) {
        float x = si + sj[j];
        x = (x > 0.f) ? x : 0.2f * x;  // leaky_relu alpha=0.2
        ev[j] = x;
        m = fmaxf(m, x);
    }
    m = fmaxf(m, __shfl_xor_sync(0xffffffffu, m, 1));
    m = fmaxf(m, __shfl_xor_sync(0xffffffffu, m, 2));
    m = fmaxf(m, __shfl_xor_sync(0xffffffffu, m, 4));
    float s = 0.f;
#pragma unroll
    for (int j = 0; j < 8; j++) {
        float e = __expf(ev[j] - m);
        ev[j] = e;
        s += e;
    }
    s += __shfl_xor_sync(0xffffffffu, s, 1);
    s += __shfl_xor_sync(0xffffffffu, s, 2);
    s += __shfl_xor_sync(0xffffffffu, s, 4);
    float inv = 1.0f / s;
    float* dst = sAt + row * ASTR + lane * 8;
#pragma unroll
    for (int j = 0; j < 8; j++) dst[j] = ev[j] * inv;
}

__device__ __forceinline__ float elu1(float x) {
    return (x > 0.f) ? x : (__expf(x) - 1.0f);
}

__global__ __launch_bounds__(NT, 2) void gat_kernel(
    const float* __restrict__ users, const float* __restrict__ W1,
    const float* __restrict__ W2,
    const float* __restrict__ mw1, const float* __restrict__ mb1,
    const float* __restrict__ mw2, const float* __restrict__ mb2,
    float* __restrict__ out, int B) {
    extern __shared__ float sm[];
    float* sWhPk = sm;                    // 32*264 = 8448 (k-interleaved Wh2)
    float* sH    = sWhPk + 32 * PSTR;     // 64*132
    float* sAt   = sH + MM * STR;         // 64*68
    float* sU    = sAt + MM * ASTR;       // 192
    float* sT    = sU + 192;              // 256 (64 x 4, T = attn1 @ U, padded)
    float* sSi   = sT + 256;              // 64
    float* sSj   = sSi + 64;              // 64
    float* sC2l  = sSj + 64;              // 128
    float* sC2r  = sC2l + 128;            // 128
    float* sPoolH= sC2r + 128;            // 256
    float* sPool = sPoolH + 256;          // 128
    float* sR    = sPool + 128;           // 32
    float* sO    = sR + 32;               // 128
    float* sSum  = sO + 128;              // 2

    const int tid  = threadIdx.x;
    const int b    = blockIdx.x;
    // GEMM decomposition: warp tile = 32 rows x 16 cols; thread = 4 rows x 4 cols
    const int warp  = tid >> 5;
    const int lane  = tid & 31;
    const int rh    = warp >> 3;          // row half
    const int octet = warp & 7;           // col octet (16 cols)
    const int rg    = lane >> 2;          // 0..7 row sub-group
    const int cp    = lane & 3;           // 0..3 col quad
    const int c0    = octet * 16 + cp * 4;
    const int r0    = rh * 32 + rg;       // rows r0 + 8*j, j=0..3

    // ---- P0: load users + c2 vectors
    if (tid < MM * INF_) sU[tid] = users[b * (MM * INF_) + tid];
    if (tid < 128) { sC2l[tid] = g_c2l[tid]; sC2r[tid] = g_c2r[tid]; }
    __syncthreads();

    // ---- P1: layer1 si/sj via c1 trick
    if (tid < MM) {
        float u0 = sU[tid * 3], u1 = sU[tid * 3 + 1], u2 = sU[tid * 3 + 2];
        sSi[tid] = u0 * g_c1l[0] + u1 * g_c1l[1] + u2 * g_c1l[2];
        sSj[tid] = u0 * g_c1r[0] + u1 * g_c1r[1] + u2 * g_c1r[2];
    }
    __syncthreads();

    // ---- P2: softmax layer 1
    softmax64_w8(sAt, sSi, sSj, tid);
    __syncthreads();

    // ---- P3a: T = attn1 @ U (64x3; rank-3 fusion)
    {
        int row = tid >> 3, l8 = tid & 7;
        const float* ar = sAt + row * ASTR + l8 * 8;
        float t0 = 0.f, t1 = 0.f, t2 = 0.f;
#pragma unroll
        for (int j = 0; j < 8; j++) {
            float a = ar[j];
            const float* u = sU + (l8 * 8 + j) * 3;
            t0 = fmaf(a, u[0], t0);
            t1 = fmaf(a, u[1], t1);
            t2 = fmaf(a, u[2], t2);
        }
#pragma unroll
        for (int off = 1; off < 8; off <<= 1) {
            t0 += __shfl_xor_sync(0xffffffffu, t0, off);
            t1 += __shfl_xor_sync(0xffffffffu, t1, off);
            t2 += __shfl_xor_sync(0xffffffffu, t2, off);
        }
        if (!l8) {
            sT[row * 4 + 0] = t0;
            sT[row * 4 + 1] = t1;
            sT[row * 4 + 2] = t2;
            sT[row * 4 + 3] = 0.f;
        }
    }
    __syncthreads();

    // ---- P3b: h = elu(T @ W1) -> sH  (K=3)
    {
        const int d = tid & 127;
        const int q = tid >> 7;
        float w0 = W1[d], w1 = W1[HH + d], w2 = W1[2 * HH + d];
        const int i0 = q * 16;
#pragma unroll
        for (int r = 0; r < 16; r++) {
            float4 t = *(const float4*)&sT[(i0 + r) * 4];
            float x = fmaf(t.x, w0, fmaf(t.y, w1, t.z * w2));
            sH[(i0 + r) * STR + d] = elu1(x);
        }
    }
    __syncthreads();

    // ---- P4: layer2 si/sj = h @ c2 (64 rows x 8 lanes)
    {
        int row = tid >> 3, l8 = tid & 7;
        const float* hr = sH + row * STR + l8 * 16;
        const float* cl = sC2l + l8 * 16;
        const float* cr = sC2r + l8 * 16;
        float s1 = 0.f, s2 = 0.f;
#pragma unroll
        for (int k = 0; k < 16; k++) {
            float hv = hr[k];
            s1 = fmaf(hv, cl[k], s1);
            s2 = fmaf(hv, cr[k], s2);
        }
        s1 += __shfl_xor_sync(0xffffffffu, s1, 1);
        s2 += __shfl_xor_sync(0xffffffffu, s2, 1);
        s1 += __shfl_xor_sync(0xffffffffu, s1, 2);
        s2 += __shfl_xor_sync(0xffffffffu, s2, 2);
        s1 += __shfl_xor_sync(0xffffffffu, s1, 4);
        s2 += __shfl_xor_sync(0xffffffffu, s2, 4);
        if (!l8) { sSi[row] = s1; sSj[row] = s2; }
    }
    // ---- P5: Wh2 = h @ W2, K=128 (64 packed steps), FFMA2, interleaved output
    {
        ull acc[4][4];
#pragma unroll
        for (int j = 0; j < 4; j++)
#pragma unroll
            for (int c = 0; c < 4; c++) acc[j][c] = 0ull;
#pragma unroll 4
        for (int pk = 0; pk < 64; pk++) {
            const float* wp = &g_W2pk[(pk * HH + c0) * 2];
            ulonglong2 w01 = *(const ulonglong2*)wp;        // cols c0, c0+1 (k-pair packed)
            ulonglong2 w23 = *(const ulonglong2*)(wp + 4);  // cols c0+2, c0+3
#pragma unroll
            for (int j = 0; j < 4; j++) {
                ull hp = *(const ull*)&sH[(r0 + 8 * j) * STR + 2 * pk];  // (h[2pk], h[2pk+1])
                ffma2(acc[j][0], hp, w01.x);
                ffma2(acc[j][1], hp, w01.y);
                ffma2(acc[j][2], hp, w23.x);
                ffma2(acc[j][3], hp, w23.y);
            }
        }
        // store into k-interleaved layout: Wh2[r][c] -> sWhPk[(r>>1)*PSTR + 2c + (r&1)]
#pragma unroll
        for (int j = 0; j < 4; j++) {
            int r = r0 + 8 * j;
            float* dst = sWhPk + (r >> 1) * PSTR + (r & 1);
#pragma unroll
            for (int c = 0; c < 4; c++) {
                float2 v = unpk(acc[j][c]);
                dst[2 * (c0 + c)] = v.x + v.y;
            }
        }
    }
    __syncthreads();

    // ---- P6: softmax layer 2
    softmax64_w8(sAt, sSi, sSj, tid);
    __syncthreads();

    // ---- P7: h2 = elu(attn2 @ Wh2), K=64 (32 packed steps), FFMA2, fused max-pool
    {
        ull acc[4][4];
#pragma unroll
        for (int j = 0; j < 4; j++)
#pragma unroll
            for (int c = 0; c < 4; c++) acc[j][c] = 0ull;
#pragma unroll 4
        for (int pk = 0; pk < 32; pk++) {
            const float* wp = &sWhPk[pk * PSTR + 2 * c0];
            ulonglong2 w01 = *(const ulonglong2*)wp;
            ulonglong2 w23 = *(const ulonglong2*)(wp + 4);
#pragma unroll
            for (int j = 0; j < 4; j++) {
                ull ap = *(const ull*)&sAt[(r0 + 8 * j) * ASTR + 2 * pk];
                ffma2(acc[j][0], ap, w01.x);
                ffma2(acc[j][1], ap, w01.y);
                ffma2(acc[j][2], ap, w23.x);
                ffma2(acc[j][3], ap, w23.y);
            }
        }
        float pc[4] = {-1e30f, -1e30f, -1e30f, -1e30f};
#pragma unroll
        for (int j = 0; j < 4; j++) {
#pragma unroll
            for (int c = 0; c < 4; c++) {
                float2 v = unpk(acc[j][c]);
                pc[c] = fmaxf(pc[c], elu1(v.x + v.y));
            }
        }
#pragma unroll
        for (int off = 4; off < 32; off <<= 1) {
#pragma unroll
            for (int c = 0; c < 4; c++)
                pc[c] = fmaxf(pc[c], __shfl_xor_sync(0xffffffffu, pc[c], off));
        }
        if (rg == 0)
            *(float4*)&sPoolH[rh * 128 + c0] = make_float4(pc[0], pc[1], pc[2], pc[3]);
    }
    __syncthreads();

    // ---- P7b: combine the two row halves
    if (tid < 128) sPool[tid] = fmaxf(sPoolH[tid], sPoolH[128 + tid]);
    __syncthreads();

    // ---- P8: hidden = relu(pooled @ mw1 + mb1)  (32 cols x 8 lanes)
    if (tid < 256) {
        int col = tid >> 3, l8 = tid & 7;
        float acc = 0.f;
        const float* pp = sPool + l8 * 16;
#pragma unroll
        for (int k = 0; k < 16; k++) acc = fmaf(pp[k], mw1[(l8 * 16 + k) * 32 + col], acc);
        acc += __shfl_xor_sync(0xffffffffu, acc, 1);
        acc += __shfl_xor_sync(0xffffffffu, acc, 2);
        acc += __shfl_xor_sync(0xffffffffu, acc, 4);
        if (!l8) sR[col] = fmaxf(acc + mb1[col], 0.f);
    }
    __syncthreads();

    // ---- P9: readout = hidden @ mw2 + mb2; relu + eps
    if (tid < 128) {
        float acc = mb2[tid];
#pragma unroll
        for (int m = 0; m < 32; m++) acc = fmaf(sR[m], mw2[m * HH + tid], acc);
        sO[tid] = fmaxf(acc, 0.f) + 1e-6f;
    }
    __syncthreads();

    // ---- P10: sums (delta = first 64, power = last 64)
    if (tid < 2) {
        float s = 0.f;
        const float* p = sO + tid * 64;
#pragma unroll 8
        for (int j = 0; j < 64; j++) s += p[j];
        sSum[tid] = s;
    }
    __syncthreads();

    // ---- P11: normalize & write. Output layout: power[B,A] then delta[B,A]
    if (tid < 128) {
        const float Bmax = 2.0f * 50.0f - 63.0f * 0.025f;  // 98.425
        const float PMAX = 1.0f;                            // 10^(30/10-3)
        if (tid < 64) {
            out[(size_t)B * AA + (size_t)b * AA + tid] = Bmax * sO[tid] / (sSum[0] + 1e-6f);
        } else {
            out[(size_t)b * AA + (tid - 64)] = PMAX * sO[tid] / (sSum[1] + 1e-6f);
        }
    }
}

static const int SMEM_FLOATS = 32 * PSTR + MM * STR + MM * ASTR + 192 + 256 + 64 + 64 + 128 + 128 + 256 + 128 + 32 + 128 + 2;

extern "C" void kernel_launch(void* const* d_in, const int* in_sizes, int n_in,
                              void* d_out, int out_size) {
    const float* users = (const float*)d_in[0];
    const float* W1    = (const float*)d_in[1];
    const float* a1    = (const float*)d_in[2];
    const float* W2    = (const float*)d_in[3];
    const float* a2    = (const float*)d_in[4];
    const float* mw1   = (const float*)d_in[5];
    const float* mb1   = (const float*)d_in[6];
    const float* mw2   = (const float*)d_in[7];
    const float* mb2   = (const float*)d_in[8];
    float* out = (float*)d_out;

    int B = in_sizes[0] / (MM * INF_);
    size_t smem = (size_t)SMEM_FLOATS * sizeof(float);

    cudaFuncSetAttribute(gat_kernel, cudaFuncAttributeMaxDynamicSharedMemorySize, (int)smem);

    precomp_kernel<<<1, 128>>>(W1, a1, W2, a2);
    gat_kernel<<<B, NT, smem>>>(users, W1, W2, mw1, mb1, mw2, mb2, out, B);
}

// round 9
// speedup vs baseline: 1.8103x; 1.8103x over previous
#include <cuda_runtime.h>
#include <cuda_bf16.h>

#define MM   64
#define HH   128
#define INF_ 3
#define AA   64
#define NT   512

#define SH_STR 136   // bf16 units; 272B row stride (≡16 mod 128)
#define AT_STR 72    // bf16 units; 144B row stride
#define WT_STR 72    // bf16 units; 144B row stride

typedef __nv_bfloat16 bf16;
typedef unsigned int uint;

__device__ float g_c2l[HH], g_c2r[HH], g_c1l[INF_], g_c1r[INF_];
// W2 pre-split (hi/lo bf16) and pre-permuted into m16n8k16 B-fragment order:
// idx = (((ks*16 + nu)*32 + lane)*2 + w); value = {W2[k][n], W2[k+1][n]} packed,
// k = ks*16 + 2*(lane&3) + 8*w, n = nu*8 + (lane>>2)
__device__ uint g_W2Bhi[8 * 16 * 32 * 2];
__device__ uint g_W2Blo[8 * 16 * 32 * 2];

__device__ __forceinline__ uint packbf(bf16 a, bf16 b) {
    __nv_bfloat162 v = __halves2bfloat162(a, b);
    return *(uint*)&v;
}

__device__ __forceinline__ void mma16816(float4& d, uint a0, uint a1, uint a2, uint a3,
                                         uint b0, uint b1) {
    asm volatile(
        "mma.sync.aligned.m16n8k16.row.col.f32.bf16.bf16.f32 "
        "{%0,%1,%2,%3}, {%4,%5,%6,%7}, {%8,%9}, {%0,%1,%2,%3};"
        : "+f"(d.x), "+f"(d.y), "+f"(d.z), "+f"(d.w)
        : "r"(a0), "r"(a1), "r"(a2), "r"(a3), "r"(b0), "r"(b1));
}

__device__ __forceinline__ void storeSplit(bf16* hi, bf16* lo, int idx, float v) {
    bf16 h = __float2bfloat16_rn(v);
    hi[idx] = h;
    lo[idx] = __float2bfloat16_rn(v - __bfloat162float(h));
}

__global__ void precomp_kernel(const float* __restrict__ W1, const float* __restrict__ a1,
                               const float* __restrict__ W2, const float* __restrict__ a2) {
    int t = threadIdx.x;  // 128 threads
    float s1 = 0.f, s2 = 0.f;
#pragma unroll 8
    for (int j = 0; j < HH; j++) {
        float w = W2[t * HH + j];
        s1 = fmaf(w, a2[j], s1);
        s2 = fmaf(w, a2[HH + j], s2);
    }
    g_c2l[t] = s1;
    g_c2r[t] = s2;
    if (t < INF_) {
        float p = 0.f, q = 0.f;
#pragma unroll 8
        for (int j = 0; j < HH; j++) {
            float w = W1[t * HH + j];
            p = fmaf(w, a1[j], p);
            q = fmaf(w, a1[HH + j], q);
        }
        g_c1l[t] = p;
        g_c1r[t] = q;
    }
    // Fragment-ordered, hi/lo-split W2
    for (int idx = t; idx < 8 * 16 * 32 * 2; idx += 128) {
        int w = idx & 1;
        int lane = (idx >> 1) & 31;
        int nu = (idx >> 6) & 15;
        int ks = idx >> 10;
        int g = lane >> 2, tt = lane & 3;
        int k = ks * 16 + 2 * tt + 8 * w;
        int n = nu * 8 + g;
        float v0 = W2[k * HH + n];
        float v1 = W2[(k + 1) * HH + n];
        bf16 h0 = __float2bfloat16_rn(v0);
        bf16 h1 = __float2bfloat16_rn(v1);
        g_W2Bhi[idx] = packbf(h0, h1);
        g_W2Blo[idx] = packbf(__float2bfloat16_rn(v0 - __bfloat162float(h0)),
                              __float2bfloat16_rn(v1 - __bfloat162float(h1)));
    }
}

// Softmax over 64 cols, 8 lanes per row; writes bf16 hi/lo attn tiles.
__device__ __forceinline__ void softmax64_bf(char* __restrict__ atHi, char* __restrict__ atLo,
                                             const float* __restrict__ sSi,
                                             const float* __restrict__ sSj, int tid) {
    int row = tid >> 3, l8 = tid & 7;
    float si = sSi[row];
    const float* sj = sSj + l8 * 8;
    float ev[8];
    float m = -1e30f;
#pragma unroll
    for (int j = 0; j < 8; j++) {
        float x = si + sj[j];
        x = (x > 0.f) ? x : 0.2f * x;
        ev[j] = x;
        m = fmaxf(m, x);
    }
    m = fmaxf(m, __shfl_xor_sync(0xffffffffu, m, 1));
    m = fmaxf(m, __shfl_xor_sync(0xffffffffu, m, 2));
    m = fmaxf(m, __shfl_xor_sync(0xffffffffu, m, 4));
    float s = 0.f;
#pragma unroll
    for (int j = 0; j < 8; j++) {
        float e = __expf(ev[j] - m);
        ev[j] = e;
        s += e;
    }
    s += __shfl_xor_sync(0xffffffffu, s, 1);
    s += __shfl_xor_sync(0xffffffffu, s, 2);
    s += __shfl_xor_sync(0xffffffffu, s, 4);
    float inv = 1.0f / s;
    uint* dh = (uint*)(atHi + row * (AT_STR * 2) + l8 * 16);
    uint* dl = (uint*)(atLo + row * (AT_STR * 2) + l8 * 16);
#pragma unroll
    for (int p = 0; p < 4; p++) {
        float v0 = ev[2 * p] * inv, v1 = ev[2 * p + 1] * inv;
        bf16 h0 = __float2bfloat16_rn(v0);
        bf16 h1 = __float2bfloat16_rn(v1);
        dh[p] = packbf(h0, h1);
        dl[p] = packbf(__float2bfloat16_rn(v0 - __bfloat162float(h0)),
                       __float2bfloat16_rn(v1 - __bfloat162float(h1)));
    }
}

__device__ __forceinline__ float elu1(float x) {
    return (x > 0.f) ? x : (__expf(x) - 1.0f);
}

__global__ __launch_bounds__(NT, 2) void gat_kernel(
    const float* __restrict__ users, const float* __restrict__ W1,
    const float* __restrict__ W2,
    const float* __restrict__ mw1, const float* __restrict__ mb1,
    const float* __restrict__ mw2, const float* __restrict__ mb2,
    float* __restrict__ out, int B) {
    extern __shared__ char smb[];
    bf16* sHhi  = (bf16*)(smb);                  // 64 x SH_STR
    bf16* sHlo  = (bf16*)(smb + 17408);
    bf16* sWthi = (bf16*)(smb + 34816);          // 128 x WT_STR (Wh2 transposed)
    bf16* sWtlo = (bf16*)(smb + 53248);
    char* atHi  = smb + 71680;                   // 64 x AT_STR bf16
    char* atLo  = smb + 80896;
    float* sF   = (float*)(smb + 90112);
    float* sU    = sF;              // 192
    float* sT    = sF + 192;        // 256
    float* sSi   = sF + 448;        // 64
    float* sSj   = sF + 512;        // 64
    float* sC2l  = sF + 576;        // 128
    float* sC2r  = sF + 704;        // 128
    float* sPoolQ= sF + 832;        // 512
    float* sPool = sF + 1344;       // 128
    float* sR    = sF + 1472;       // 32
    float* sO    = sF + 1504;       // 128
    float* sSum  = sF + 1632;       // 2

    const int tid  = threadIdx.x;
    const int b    = blockIdx.x;
    const int warp = tid >> 5;
    const int lane = tid & 31;
    const int mi   = warp & 3;           // m16 strip
    const int nb   = warp >> 2;          // n32 block
    const int g    = lane >> 2;
    const int t4   = lane & 3;

    // ---- P0
    if (tid < MM * INF_) sU[tid] = users[b * (MM * INF_) + tid];
    if (tid < 128) { sC2l[tid] = g_c2l[tid]; sC2r[tid] = g_c2r[tid]; }
    __syncthreads();

    // ---- P1: layer1 si/sj via c1 trick
    if (tid < MM) {
        float u0 = sU[tid * 3], u1 = sU[tid * 3 + 1], u2 = sU[tid * 3 + 2];
        sSi[tid] = u0 * g_c1l[0] + u1 * g_c1l[1] + u2 * g_c1l[2];
        sSj[tid] = u0 * g_c1r[0] + u1 * g_c1r[1] + u2 * g_c1r[2];
    }
    __syncthreads();

    // ---- P2: softmax layer 1 -> attn bf16 hi/lo
    softmax64_bf(atHi, atLo, sSi, sSj, tid);
    __syncthreads();

    // ---- P3a: T = attn1 @ U (rank-3 fusion)
    {
        int row = tid >> 3, l8 = tid & 7;
        const __nv_bfloat162* ah = (const __nv_bfloat162*)(atHi + row * (AT_STR * 2) + l8 * 16);
        const __nv_bfloat162* al = (const __nv_bfloat162*)(atLo + row * (AT_STR * 2) + l8 * 16);
        float t0 = 0.f, t1 = 0.f, t2 = 0.f;
#pragma unroll
        for (int p = 0; p < 4; p++) {
            __nv_bfloat162 h2 = ah[p], l2 = al[p];
            float a0 = __bfloat162float(h2.x) + __bfloat162float(l2.x);
            float a1 = __bfloat162float(h2.y) + __bfloat162float(l2.y);
            const float* u0 = sU + (l8 * 8 + 2 * p) * 3;
            t0 = fmaf(a0, u0[0], t0); t1 = fmaf(a0, u0[1], t1); t2 = fmaf(a0, u0[2], t2);
            t0 = fmaf(a1, u0[3], t0); t1 = fmaf(a1, u0[4], t1); t2 = fmaf(a1, u0[5], t2);
        }
#pragma unroll
        for (int off = 1; off < 8; off <<= 1) {
            t0 += __shfl_xor_sync(0xffffffffu, t0, off);
            t1 += __shfl_xor_sync(0xffffffffu, t1, off);
            t2 += __shfl_xor_sync(0xffffffffu, t2, off);
        }
        if (!l8) {
            sT[row * 4 + 0] = t0;
            sT[row * 4 + 1] = t1;
            sT[row * 4 + 2] = t2;
            sT[row * 4 + 3] = 0.f;
        }
    }
    __syncthreads();

    // ---- P3b: h = elu(T @ W1) -> sHhi/sHlo (bf16 split)
    {
        const int d = tid & 127;
        const int q = tid >> 7;
        float w0 = W1[d], w1 = W1[HH + d], w2 = W1[2 * HH + d];
        const int i0 = q * 16;
#pragma unroll
        for (int r = 0; r < 16; r++) {
            float4 tt = *(const float4*)&sT[(i0 + r) * 4];
            float x = elu1(fmaf(tt.x, w0, fmaf(tt.y, w1, tt.z * w2)));
            storeSplit(sHhi, sHlo, (i0 + r) * SH_STR + d, x);
        }
    }
    __syncthreads();

    // ---- P4: layer2 si/sj = h @ c2
    {
        int row = tid >> 3, l8 = tid & 7;
        const __nv_bfloat162* hh = (const __nv_bfloat162*)(sHhi + row * SH_STR + l8 * 16);
        const __nv_bfloat162* hl = (const __nv_bfloat162*)(sHlo + row * SH_STR + l8 * 16);
        const float* cl = sC2l + l8 * 16;
        const float* cr = sC2r + l8 * 16;
        float s1 = 0.f, s2 = 0.f;
#pragma unroll
        for (int p = 0; p < 8; p++) {
            __nv_bfloat162 h2 = hh[p], l2 = hl[p];
            float h0 = __bfloat162float(h2.x) + __bfloat162float(l2.x);
            float h1 = __bfloat162float(h2.y) + __bfloat162float(l2.y);
            s1 = fmaf(h0, cl[2 * p], s1);     s2 = fmaf(h0, cr[2 * p], s2);
            s1 = fmaf(h1, cl[2 * p + 1], s1); s2 = fmaf(h1, cr[2 * p + 1], s2);
        }
        s1 += __shfl_xor_sync(0xffffffffu, s1, 1);
        s2 += __shfl_xor_sync(0xffffffffu, s2, 1);
        s1 += __shfl_xor_sync(0xffffffffu, s1, 2);
        s2 += __shfl_xor_sync(0xffffffffu, s2, 2);
        s1 += __shfl_xor_sync(0xffffffffu, s1, 4);
        s2 += __shfl_xor_sync(0xffffffffu, s2, 4);
        if (!l8) { sSi[row] = s1; sSj[row] = s2; }
    }
    // ---- P5: Wh2 = h @ W2 via bf16x3 tensor MMA; writes transposed hi/lo
    {
        const int arow = mi * 16 + g;
        float4 acc[4];
#pragma unroll
        for (int f = 0; f < 4; f++) acc[f] = make_float4(0.f, 0.f, 0.f, 0.f);
#pragma unroll
        for (int ks = 0; ks < 8; ks++) {
            int kb = ks * 16 + 2 * t4;
            uint ah0 = *(const uint*)&sHhi[arow * SH_STR + kb];
            uint ah1 = *(const uint*)&sHhi[(arow + 8) * SH_STR + kb];
            uint ah2 = *(const uint*)&sHhi[arow * SH_STR + kb + 8];
            uint ah3 = *(const uint*)&sHhi[(arow + 8) * SH_STR + kb + 8];
            uint al0 = *(const uint*)&sHlo[arow * SH_STR + kb];
            uint al1 = *(const uint*)&sHlo[(arow + 8) * SH_STR + kb];
            uint al2 = *(const uint*)&sHlo[arow * SH_STR + kb + 8];
            uint al3 = *(const uint*)&sHlo[(arow + 8) * SH_STR + kb + 8];
#pragma unroll
            for (int f = 0; f < 4; f++) {
                int nu = nb * 4 + f;
                int bidx = ((ks * 16 + nu) * 32 + lane) * 2;
                uint2 bh = *(const uint2*)&g_W2Bhi[bidx];
                uint2 bl = *(const uint2*)&g_W2Blo[bidx];
                mma16816(acc[f], ah0, ah1, ah2, ah3, bh.x, bh.y);
                mma16816(acc[f], ah0, ah1, ah2, ah3, bl.x, bl.y);
                mma16816(acc[f], al0, al1, al2, al3, bh.x, bh.y);
            }
        }
#pragma unroll
        for (int f = 0; f < 4; f++) {
            int c = nb * 32 + f * 8 + 2 * t4;
            storeSplit(sWthi, sWtlo, c * WT_STR + arow,           acc[f].x);
            storeSplit(sWthi, sWtlo, (c + 1) * WT_STR + arow,     acc[f].y);
            storeSplit(sWthi, sWtlo, c * WT_STR + arow + 8,       acc[f].z);
            storeSplit(sWthi, sWtlo, (c + 1) * WT_STR + arow + 8, acc[f].w);
        }
    }
    __syncthreads();

    // ---- P6: softmax layer 2 -> attn bf16 hi/lo
    softmax64_bf(atHi, atLo, sSi, sSj, tid);
    __syncthreads();

    // ---- P7: h2 = elu(attn2 @ Wh2) via bf16x3 MMA, fused max-pool
    {
        const int arow = mi * 16 + g;
        float4 acc[4];
#pragma unroll
        for (int f = 0; f < 4; f++) acc[f] = make_float4(0.f, 0.f, 0.f, 0.f);
#pragma unroll
        for (int ks = 0; ks < 4; ks++) {
            int kb = ks * 16 + 2 * t4;
            uint ah0 = *(const uint*)(atHi + arow * (AT_STR * 2) + kb * 2);
            uint ah1 = *(const uint*)(atHi + (arow + 8) * (AT_STR * 2) + kb * 2);
            uint ah2 = *(const uint*)(atHi + arow * (AT_STR * 2) + kb * 2 + 16);
            uint ah3 = *(const uint*)(atHi + (arow + 8) * (AT_STR * 2) + kb * 2 + 16);
            uint al0 = *(const uint*)(atLo + arow * (AT_STR * 2) + kb * 2);
            uint al1 = *(const uint*)(atLo + (arow + 8) * (AT_STR * 2) + kb * 2);
            uint al2 = *(const uint*)(atLo + arow * (AT_STR * 2) + kb * 2 + 16);
            uint al3 = *(const uint*)(atLo + (arow + 8) * (AT_STR * 2) + kb * 2 + 16);
#pragma unroll
            for (int f = 0; f < 4; f++) {
                int nu = nb * 4 + f;
                uint b0h = *(const uint*)&sWthi[(nu * 8 + g) * WT_STR + kb];
                uint b1h = *(const uint*)&sWthi[(nu * 8 + g) * WT_STR + kb + 8];
                uint b0l = *(const uint*)&sWtlo[(nu * 8 + g) * WT_STR + kb];
                uint b1l = *(const uint*)&sWtlo[(nu * 8 + g) * WT_STR + kb + 8];
                mma16816(acc[f], ah0, ah1, ah2, ah3, b0h, b1h);
                mma16816(acc[f], ah0, ah1, ah2, ah3, b0l, b1l);
                mma16816(acc[f], al0, al1, al2, al3, b0h, b1h);
            }
        }
#pragma unroll
        for (int f = 0; f < 4; f++) {
            float p0 = fmaxf(elu1(acc[f].x), elu1(acc[f].z));
            float p1 = fmaxf(elu1(acc[f].y), elu1(acc[f].w));
#pragma unroll
            for (int off = 4; off < 32; off <<= 1) {
                p0 = fmaxf(p0, __shfl_xor_sync(0xffffffffu, p0, off));
                p1 = fmaxf(p1, __shfl_xor_sync(0xffffffffu, p1, off));
            }
            if (lane < 4) {
                int c = nb * 32 + f * 8 + 2 * lane;
                *(float2*)&sPoolQ[mi * 128 + c] = make_float2(p0, p1);
            }
        }
    }
    __syncthreads();

    // ---- P7b: combine the four m-strips
    if (tid < 128) {
        float p0 = sPoolQ[tid], p1 = sPoolQ[128 + tid];
        float p2 = sPoolQ[256 + tid], p3 = sPoolQ[384 + tid];
        sPool[tid] = fmaxf(fmaxf(p0, p1), fmaxf(p2, p3));
    }
    __syncthreads();

    // ---- P8: hidden = relu(pooled @ mw1 + mb1)
    if (tid < 256) {
        int col = tid >> 3, l8 = tid & 7;
        float acc = 0.f;
        const float* pp = sPool + l8 * 16;
#pragma unroll
        for (int k = 0; k < 16; k++) acc = fmaf(pp[k], mw1[(l8 * 16 + k) * 32 + col], acc);
        acc += __shfl_xor_sync(0xffffffffu, acc, 1);
        acc += __shfl_xor_sync(0xffffffffu, acc, 2);
        acc += __shfl_xor_sync(0xffffffffu, acc, 4);
        if (!l8) sR[col] = fmaxf(acc + mb1[col], 0.f);
    }
    __syncthreads();

    // ---- P9
    if (tid < 128) {
        float acc = mb2[tid];
#pragma unroll
        for (int m = 0; m < 32; m++) acc = fmaf(sR[m], mw2[m * HH + tid], acc);
        sO[tid] = fmaxf(acc, 0.f) + 1e-6f;
    }
    __syncthreads();

    // ---- P10
    if (tid < 2) {
        float s = 0.f;
        const float* p = sO + tid * 64;
#pragma unroll 8
        for (int j = 0; j < 64; j++) s += p[j];
        sSum[tid] = s;
    }
    __syncthreads();

    // ---- P11: normalize & write. power[B,A] then delta[B,A]
    if (tid < 128) {
        const float Bmax = 2.0f * 50.0f - 63.0f * 0.025f;  // 98.425
        const float PMAX = 1.0f;
        if (tid < 64) {
            out[(size_t)B * AA + (size_t)b * AA + tid] = Bmax * sO[tid] / (sSum[0] + 1e-6f);
        } else {
            out[(size_t)b * AA + (tid - 64)] = PMAX * sO[tid] / (sSum[1] + 1e-6f);
        }
    }
}

static const int SMEM_BYTES = 96768;

extern "C" void kernel_launch(void* const* d_in, const int* in_sizes, int n_in,
                              void* d_out, int out_size) {
    const float* users = (const float*)d_in[0];
    const float* W1    = (const float*)d_in[1];
    const float* a1    = (const float*)d_in[2];
    const float* W2    = (const float*)d_in[3];
    const float* a2    = (const float*)d_in[4];
    const float* mw1   = (const float*)d_in[5];
    const float* mb1   = (const float*)d_in[6];
    const float* mw2   = (const float*)d_in[7];
    const float* mb2   = (const float*)d_in[8];
    float* out = (float*)d_out;

    int B = in_sizes[0] / (MM * INF_);

    cudaFuncSetAttribute(gat_kernel, cudaFuncAttributeMaxDynamicSharedMemorySize, SMEM_BYTES);

    precomp_kernel<<<1, 128>>>(W1, a1, W2, a2);
    gat_kernel<<<B, NT, SMEM_BYTES>>>(users, W1, W2, mw1, mb1, mw2, mb2, out, B);
}